// round 15
// baseline (speedup 1.0000x reference)
#include <cuda_runtime.h>
#include <cuda_fp16.h>
#include <cstdint>

// Nonlocal block: N=4, C=512, CI=256, S=6272. fp16 mma.sync everywhere.
// R15: outproj redesigned — A (3-way partial sum) loaded once per 64-s CTA,
// W double-buffered via cp.async (128ci x 128c tiles), Ps staging unaliased.
// Attention and projection unchanged from R14.
#define NB      4
#define C_DIM   512
#define CI_DIM  256
#define S_DIM   6272
#define BN_EPS  1e-5f
#define BN_CNT  25088.0f
#define SCL_TH  0.09016844f   // (1/16) * log2(e)
#define ONESH2  0x3C003C00u   // half2(1.0, 1.0)
#define KSPLIT  3
#define KT01    33

// ---- scratch ----
__device__ __half g_Qh[NB * S_DIM * CI_DIM];
__device__ __half g_Kh[NB * S_DIM * CI_DIM];
__device__ __half g_Vh[NB * S_DIM * CI_DIM];
__device__ __half g_Oph[KSPLIT * NB * S_DIM * CI_DIM];  // fp16 partial O
__device__ float  g_RSp[KSPLIT * NB * S_DIM];
__device__ __half g_Ph[NB * C_DIM * S_DIM];             // pre-BN, fp16
__device__ __half g_wAllh[C_DIM * 768];
__device__ __half g_woTh [CI_DIM * C_DIM];
__device__ float  g_bAll[768];
__device__ float  g_sum[C_DIM];
__device__ float  g_sumsq[C_DIM];
__device__ float  g_scale[C_DIM];
__device__ float  g_shift[C_DIM];

// ---- helpers ----
__device__ __forceinline__ uint32_t smem_u32(const void* p) {
    uint32_t a;
    asm("{ .reg .u64 t; cvta.to.shared.u64 t, %1; cvt.u32.u64 %0, t; }" : "=r"(a) : "l"(p));
    return a;
}
__device__ __forceinline__ uint32_t packh2(float lo, float hi) {
    uint32_t r;
    asm("cvt.rn.f16x2.f32 %0, %1, %2;" : "=r"(r) : "f"(hi), "f"(lo));
    return r;
}
__device__ __forceinline__ uint32_t ex2h2(uint32_t x) {
    uint32_t r;
    asm("ex2.approx.f16x2 %0, %1;" : "=r"(r) : "r"(x));
    return r;
}
__device__ __forceinline__ uint32_t haddu(uint32_t a, uint32_t b) {
    uint32_t r;
    asm("add.f16x2 %0, %1, %2;" : "=r"(r) : "r"(a), "r"(b));
    return r;
}
__device__ __forceinline__ void ldm4(uint32_t& r0, uint32_t& r1, uint32_t& r2, uint32_t& r3,
                                     uint32_t a) {
    asm volatile("ldmatrix.sync.aligned.m8n8.x4.shared.b16 {%0,%1,%2,%3}, [%4];"
                 : "=r"(r0), "=r"(r1), "=r"(r2), "=r"(r3) : "r"(a));
}
__device__ __forceinline__ void ldm4t(uint32_t& r0, uint32_t& r1, uint32_t& r2, uint32_t& r3,
                                      uint32_t a) {
    asm volatile("ldmatrix.sync.aligned.m8n8.x4.trans.shared.b16 {%0,%1,%2,%3}, [%4];"
                 : "=r"(r0), "=r"(r1), "=r"(r2), "=r"(r3) : "r"(a));
}
__device__ __forceinline__ void mmah(float* d, uint32_t a0, uint32_t a1, uint32_t a2,
                                     uint32_t a3, uint32_t b0, uint32_t b1) {
    asm volatile(
        "mma.sync.aligned.m16n8k16.row.col.f32.f16.f16.f32 "
        "{%0,%1,%2,%3}, {%4,%5,%6,%7}, {%8,%9}, {%0,%1,%2,%3};"
        : "+f"(d[0]), "+f"(d[1]), "+f"(d[2]), "+f"(d[3])
        : "r"(a0), "r"(a1), "r"(a2), "r"(a3), "r"(b0), "r"(b1));
}
__device__ __forceinline__ void cpa16(uint32_t dst, const void* src) {
    asm volatile("cp.async.cg.shared.global [%0], [%1], 16;" :: "r"(dst), "l"(src));
}
#define CP_COMMIT() asm volatile("cp.async.commit_group;" ::: "memory")
#define CP_WAIT0()  asm volatile("cp.async.wait_group 0;" ::: "memory")
#define BARP(id)    asm volatile("bar.sync %0, 64;" :: "r"(id) : "memory")
#define SW(row, c8, rowbytes) ((row) * (rowbytes) + ((((c8)) ^ ((row) & 7)) << 4))

// ======================= K0a: coalesced weight transpose =======================
__global__ void transpose_kernel(const float* __restrict__ wth, const float* __restrict__ wph,
                                 const float* __restrict__ wg,  const float* __restrict__ wout) {
    __shared__ float tile[32][33];
    int b = blockIdx.x;
    int tx = threadIdx.x & 31, ty = threadIdx.x >> 5;
    if (b < 384) {
        int m = b >> 7;
        int t = b & 127;
        int o0 = (t >> 4) << 5;
        int c0 = (t & 15) << 5;
        const float* src = (m == 0) ? wth : (m == 1) ? wph : wg;
#pragma unroll
        for (int i = 0; i < 4; i++) {
            int r = ty + i * 8;
            tile[r][tx] = src[(size_t)(o0 + r) * 512 + c0 + tx];
        }
        __syncthreads();
#pragma unroll
        for (int i = 0; i < 4; i++) {
            int r = ty + i * 8;
            g_wAllh[(size_t)(c0 + r) * 768 + m * 256 + o0 + tx] = __float2half(tile[tx][r]);
        }
    } else {
        int t = b - 384;
        int r0 = (t >> 3) << 5;
        int c0 = (t & 7) << 5;
#pragma unroll
        for (int i = 0; i < 4; i++) {
            int r = ty + i * 8;
            tile[r][tx] = wout[(size_t)(r0 + r) * 256 + c0 + tx];
        }
        __syncthreads();
#pragma unroll
        for (int i = 0; i < 4; i++) {
            int r = ty + i * 8;
            g_woTh[(size_t)(c0 + r) * 512 + r0 + tx] = __float2half(tile[tx][r]);
        }
    }
}

// ======================= K0b: init =======================
__global__ void init_kernel(const float* __restrict__ bth, const float* __restrict__ bph,
                            const float* __restrict__ bg) {
    int idx = blockIdx.x * 256 + threadIdx.x;
    if (idx < 768)
        g_bAll[idx] = (idx < 256) ? bth[idx] * SCL_TH
                    : (idx < 512) ? bph[idx - 256] : bg[idx - 512];
    if (idx < C_DIM) { g_sum[idx] = 0.0f; g_sumsq[idx] = 0.0f; }
    g_RSp[idx] = 0.0f;
}

// ======================= K1: QKV projection =======================
#define XS_ 0
#define WB0 65536
#define WB1 81920
#define PROJ_SMEM 98304
__global__ void __launch_bounds__(256, 2)
projh_kernel(const float* __restrict__ x) {
    extern __shared__ char sm[];
    const uint32_t sb = smem_u32(sm);
    const int tid = threadIdx.x, lane = tid & 31, w = tid >> 5;
    const int wm = w & 1, wn = w >> 1;
    const int lo3 = (lane >> 3) & 1, hi4 = lane >> 4;
    const int s0 = blockIdx.x * 64, n = blockIdx.y;
    const float* xn = x + (size_t)n * C_DIM * S_DIM;

#pragma unroll
    for (int it = 0; it < 32; it++) {
        int idx = tid + it * 256;
        int row = idx >> 4, s4 = idx & 15;
        float4 v = *(const float4*)(xn + (size_t)row * S_DIM + s0 + s4 * 4);
        half2* p = (half2*)(sm + XS_ + SW(row, s4 >> 1, 128) + (s4 & 1) * 8);
        p[0] = __floats2half2_rn(v.x, v.y);
        p[1] = __floats2half2_rn(v.z, v.w);
    }
#pragma unroll
    for (int it = 0; it < 4; it++) {
        int idx = tid + it * 256;
        int rowc = idx >> 4, c8 = idx & 15;
        cpa16(sb + WB0 + SW(rowc, c8, 256), g_wAllh + (size_t)rowc * 768 + c8 * 8);
    }
    CP_COMMIT();

    const int rAx = (lane & 7) + hi4 * 8;
    const int rBw = (lane & 7) + lo3 * 8;
    const int gq = lane >> 2, tq = lane & 3;

    for (int ob = 0; ob < 6; ob++) {
        float C[2][4][4];
#pragma unroll
        for (int i = 0; i < 2; i++)
#pragma unroll
            for (int j = 0; j < 4; j++)
#pragma unroll
                for (int k = 0; k < 4; k++) C[i][j][k] = 0.0f;

        for (int cs = 0; cs < 8; cs++) {
            int j = ob * 8 + cs;
            const uint32_t wb = (j & 1) ? WB1 : WB0;
            CP_WAIT0();
            __syncthreads();
            if (j < 47) {
                const uint32_t wb2 = (j & 1) ? WB0 : WB1;
                int j1 = j + 1;
                int ob1 = j1 >> 3, cs1 = j1 & 7;
#pragma unroll
                for (int it = 0; it < 4; it++) {
                    int idx = tid + it * 256;
                    int rowc = idx >> 4, c8 = idx & 15;
                    cpa16(sb + wb2 + SW(rowc, c8, 256),
                          g_wAllh + (size_t)(cs1 * 64 + rowc) * 768 + ob1 * 128 + c8 * 8);
                }
                CP_COMMIT();
            }
#pragma unroll
            for (int kk = 0; kk < 4; kk++) {
                uint32_t a[2][4];
#pragma unroll
                for (int mt = 0; mt < 2; mt++)
                    ldm4t(a[mt][0], a[mt][1], a[mt][2], a[mt][3],
                          sb + XS_ + SW(cs * 64 + kk * 16 + rAx,
                                        wm * 4 + mt * 2 + lo3, 128));
#pragma unroll
                for (int nb = 0; nb < 2; nb++) {
                    uint32_t b0, b1, b2, b3;
                    ldm4t(b0, b1, b2, b3,
                          sb + wb + SW(kk * 16 + rBw, wn * 4 + nb * 2 + hi4, 256));
#pragma unroll
                    for (int mt = 0; mt < 2; mt++) {
                        mmah(C[mt][2 * nb],     a[mt][0], a[mt][1], a[mt][2], a[mt][3], b0, b1);
                        mmah(C[mt][2 * nb + 1], a[mt][0], a[mt][1], a[mt][2], a[mt][3], b2, b3);
                    }
                }
            }
        }
        const float osc = (ob < 2) ? SCL_TH : 1.0f;
        const int buf = ob >> 1;
        __half* outb = (buf == 0) ? g_Qh : (buf == 1) ? g_Kh : g_Vh;
        const int colbase = (ob & 1) * 128;
#pragma unroll
        for (int mt = 0; mt < 2; mt++) {
            int srow = s0 + wm * 32 + mt * 16 + gq;
            __half* p0 = outb + ((size_t)n * S_DIM + srow) * CI_DIM + colbase;
            __half* p8 = p0 + 8 * CI_DIM;
#pragma unroll
            for (int nt = 0; nt < 4; nt++) {
                int oloc = wn * 32 + nt * 8 + 2 * tq;
                float bb0 = g_bAll[ob * 128 + oloc], bb1 = g_bAll[ob * 128 + oloc + 1];
                float* c = C[mt][nt];
                *(half2*)(p0 + oloc) = __floats2half2_rn(c[0] * osc + bb0, c[1] * osc + bb1);
                *(half2*)(p8 + oloc) = __floats2half2_rn(c[2] * osc + bb0, c[3] * osc + bb1);
            }
        }
    }
}

// ======================= K2: fp16 flash attention (key-split-3) =======================
#define AQ   0
#define BUF0 65536
#define BUF1 131072
#define AP   196608
#define ATTN_SMEM 212992
__global__ void __launch_bounds__(256, 1)
attn_kernel() {
    extern __shared__ char sm[];
    const uint32_t sb = smem_u32(sm);
    const int tid = threadIdx.x, lane = tid & 31, w = tid >> 5;
    const int hf = w >> 2;
    const int mb = (w + hf) & 3;
    const int g = lane >> 2, t = lane & 3;
    const int lo3 = (lane >> 3) & 1, hi4 = lane >> 4;
    const int s0 = blockIdx.x * 128;
    const int bh = blockIdx.y;
    const int n  = blockIdx.z;
    const int ntile = (bh < 2) ? KT01 : (98 - 2 * KT01);
    const int kb0 = bh * KT01 * 64;
    const __half* Qg = g_Qh + (size_t)n * S_DIM * CI_DIM;
    const __half* Kg = g_Kh + (size_t)n * S_DIM * CI_DIM;
    const __half* Vg = g_Vh + (size_t)n * S_DIM * CI_DIM;

#pragma unroll
    for (int it = 0; it < 16; it++) {
        int idx = tid + it * 256;
        int row = idx >> 5, c8 = idx & 31;
        cpa16(sb + AQ + SW(row, c8, 512),
              Qg + (size_t)(s0 + row) * CI_DIM + c8 * 8);
    }
#pragma unroll
    for (int it = 0; it < 8; it++) {
        int idx = tid + it * 256;
        int r = idx >> 5, c8 = idx & 31;
        uint32_t off = SW(r, c8, 512);
        cpa16(sb + BUF0 + off,         Kg + (size_t)(kb0 + r) * CI_DIM + c8 * 8);
        cpa16(sb + BUF0 + 32768 + off, Vg + (size_t)(kb0 + r) * CI_DIM + c8 * 8);
    }
    CP_COMMIT();

    float O[2][16][4];
#pragma unroll
    for (int mt = 0; mt < 2; mt++)
#pragma unroll
        for (int i = 0; i < 16; i++)
#pragma unroll
            for (int j = 0; j < 4; j++) O[mt][i][j] = 0.0f;
    float Ors[2][4];
#pragma unroll
    for (int mt = 0; mt < 2; mt++)
#pragma unroll
        for (int j = 0; j < 4; j++) Ors[mt][j] = 0.0f;

    const int rA  = mb * 32 + (lane & 7) + lo3 * 8;
    const int rK  = hf * 32 + (lane & 7) + hi4 * 8;
    const int rV  = (lane & 7) + lo3 * 8;
    const int rP  = mb * 32 + (lane & 7) + lo3 * 8;

    for (int kt = 0; kt < ntile; kt++) {
        const uint32_t bk = (kt & 1) ? BUF1 : BUF0;
        CP_WAIT0();
        __syncthreads();
        if (kt < ntile - 1) {
            const uint32_t bn_ = (kt & 1) ? BUF0 : BUF1;
            int ks1 = kb0 + (kt + 1) * 64;
#pragma unroll
            for (int it = 0; it < 8; it++) {
                int idx = tid + it * 256;
                int r = idx >> 5, c8 = idx & 31;
                uint32_t off = SW(r, c8, 512);
                cpa16(sb + bn_ + off,         Kg + (size_t)(ks1 + r) * CI_DIM + c8 * 8);
                cpa16(sb + bn_ + 32768 + off, Vg + (size_t)(ks1 + r) * CI_DIM + c8 * 8);
            }
            CP_COMMIT();
        }
        // ---- GEMM1: S(32q x 32k) = Q[mb] K[hf]^T ----
        float S[2][4][4];
#pragma unroll
        for (int mt = 0; mt < 2; mt++)
#pragma unroll
            for (int i = 0; i < 4; i++)
#pragma unroll
                for (int j = 0; j < 4; j++) S[mt][i][j] = 0.0f;
#pragma unroll
        for (int kk = 0; kk < 16; kk++) {
            uint32_t a[2][4];
#pragma unroll
            for (int mt = 0; mt < 2; mt++)
                ldm4(a[mt][0], a[mt][1], a[mt][2], a[mt][3],
                     sb + AQ + SW(rA + mt * 16, kk * 2 + hi4, 512));
#pragma unroll
            for (int j = 0; j < 2; j++) {
                uint32_t b0, b1, b2, b3;
                ldm4(b0, b1, b2, b3, sb + bk + SW(rK + j * 16, kk * 2 + lo3, 512));
#pragma unroll
                for (int mt = 0; mt < 2; mt++) {
                    mmah(S[mt][2 * j],     a[mt][0], a[mt][1], a[mt][2], a[mt][3], b0, b1);
                    mmah(S[mt][2 * j + 1], a[mt][0], a[mt][1], a[mt][2], a[mt][3], b2, b3);
                }
            }
        }
        // ---- exp (f16x2 SFU), ones-MMA rowsum, P -> smem ----
        uint32_t pk[2][4][2];
#pragma unroll
        for (int mt = 0; mt < 2; mt++) {
#pragma unroll
            for (int nt = 0; nt < 4; nt++) {
                pk[mt][nt][0] = ex2h2(packh2(S[mt][nt][0], S[mt][nt][1]));
                pk[mt][nt][1] = ex2h2(packh2(S[mt][nt][2], S[mt][nt][3]));
            }
            mmah(Ors[mt], pk[mt][0][0], pk[mt][0][1], pk[mt][1][0], pk[mt][1][1],
                 ONESH2, ONESH2);
            mmah(Ors[mt], pk[mt][2][0], pk[mt][2][1], pk[mt][3][0], pk[mt][3][1],
                 ONESH2, ONESH2);
#pragma unroll
            for (int nt = 0; nt < 4; nt++) {
                int r0 = mb * 32 + mt * 16 + g;
                int c8p = hf * 4 + nt;
                *(uint32_t*)(sm + AP + SW(r0, c8p, 128) + t * 4)     = pk[mt][nt][0];
                *(uint32_t*)(sm + AP + SW(r0 + 8, c8p, 128) + t * 4) = pk[mt][nt][1];
            }
        }
        // ---- preload V fragments for kk2=0 ----
        uint32_t vb[8][4];
#pragma unroll
        for (int nb = 0; nb < 8; nb++)
            ldm4t(vb[nb][0], vb[nb][1], vb[nb][2], vb[nb][3],
                  sb + bk + 32768 + SW(rV, hf * 16 + nb * 2 + hi4, 512));
        BARP(mb + 1);
        // ---- GEMM2 kk2=0 from preloaded fragments ----
        {
            uint32_t a[2][4];
#pragma unroll
            for (int mt = 0; mt < 2; mt++)
                ldm4(a[mt][0], a[mt][1], a[mt][2], a[mt][3],
                     sb + AP + SW(rP + mt * 16, hi4, 128));
#pragma unroll
            for (int nb = 0; nb < 8; nb++)
#pragma unroll
                for (int mt = 0; mt < 2; mt++) {
                    mmah(O[mt][2 * nb],     a[mt][0], a[mt][1], a[mt][2], a[mt][3],
                         vb[nb][0], vb[nb][1]);
                    mmah(O[mt][2 * nb + 1], a[mt][0], a[mt][1], a[mt][2], a[mt][3],
                         vb[nb][2], vb[nb][3]);
                }
        }
        // ---- GEMM2 kk2=1..3 ----
#pragma unroll
        for (int kk2 = 1; kk2 < 4; kk2++) {
            uint32_t a[2][4];
#pragma unroll
            for (int mt = 0; mt < 2; mt++)
                ldm4(a[mt][0], a[mt][1], a[mt][2], a[mt][3],
                     sb + AP + SW(rP + mt * 16, kk2 * 2 + hi4, 128));
            int rVk = rV + kk2 * 16;
#pragma unroll
            for (int nb = 0; nb < 8; nb++) {
                uint32_t b0, b1, b2, b3;
                ldm4t(b0, b1, b2, b3,
                      sb + bk + 32768 + SW(rVk, hf * 16 + nb * 2 + hi4, 512));
#pragma unroll
                for (int mt = 0; mt < 2; mt++) {
                    mmah(O[mt][2 * nb],     a[mt][0], a[mt][1], a[mt][2], a[mt][3], b0, b1);
                    mmah(O[mt][2 * nb + 1], a[mt][0], a[mt][1], a[mt][2], a[mt][3], b2, b3);
                }
            }
        }
    }
    // ---- epilogue ----
    float* RSp = g_RSp + ((size_t)bh * NB + n) * S_DIM + s0;
    if (t == 0) {
#pragma unroll
        for (int mt = 0; mt < 2; mt++) {
            atomicAdd(&RSp[mb * 32 + mt * 16 + g],     Ors[mt][0]);
            atomicAdd(&RSp[mb * 32 + mt * 16 + g + 8], Ors[mt][2]);
        }
    }
    __half* Op = g_Oph + (((size_t)bh * NB + n) * S_DIM + s0) * CI_DIM;
#pragma unroll
    for (int mt = 0; mt < 2; mt++) {
        int r0 = mb * 32 + mt * 16 + g;
#pragma unroll
        for (int nt = 0; nt < 16; nt++) {
            int col = hf * 128 + nt * 8 + 2 * t;
            *(uint32_t*)&Op[(size_t)r0 * CI_DIM + col] =
                packh2(O[mt][nt][0], O[mt][nt][1]);
            *(uint32_t*)&Op[(size_t)(r0 + 8) * CI_DIM + col] =
                packh2(O[mt][nt][2], O[mt][nt][3]);
        }
    }
}

// ======================= K3: out projection (A summed once, W pipelined) =======================
// CTA: 64 s rows x all 512 c. A = 3-way partial sum (loaded once, 32KB);
// W 128ci x 128c tiles double-buffered via cp.async; Ps staging unaliased.
#define OA    0
#define OWB0  32768
#define OWB1  65536
#define OPS   98304
#define OINV  133120
#define OUTP_SMEM 133376
__global__ void __launch_bounds__(256, 1)
outproj_kernel(const float* __restrict__ b_out) {
    extern __shared__ char sm[];
    const uint32_t sb = smem_u32(sm);
    const int tid = threadIdx.x, lane = tid & 31, w = tid >> 5;
    const int wm = w & 1, wn = w >> 1;
    const int lo3 = (lane >> 3) & 1, hi4 = lane >> 4;
    const int s0 = blockIdx.x * 64, n = blockIdx.y;
    const size_t STR = (size_t)NB * S_DIM * CI_DIM;
    const __half* Opm = g_Oph + ((size_t)n * S_DIM + s0) * CI_DIM;
    float* invs = (float*)(sm + OINV);
    float* Ps = (float*)(sm + OPS);   // [128 c][68 s]

    if (tid < 64) {
        int s_lin = n * S_DIM + s0 + tid;
        float r = g_RSp[s_lin] + g_RSp[NB * S_DIM + s_lin]
                + g_RSp[2 * NB * S_DIM + s_lin];
        invs[tid] = 1.0f / r;
    }
    // A: 64 s-rows x 256 ci, summed over 3 partials, swizzled rowbytes 512
#pragma unroll
    for (int it = 0; it < 8; it++) {
        int idx = tid + it * 256;
        int row = idx >> 5, c8 = idx & 31;
        const __half* basep = Opm + (size_t)row * CI_DIM + c8 * 8;
        uint4 ua = *(const uint4*)basep;
        uint4 ub = *(const uint4*)(basep + STR);
        uint4 uc = *(const uint4*)(basep + 2 * STR);
        uint4 us;
        us.x = haddu(haddu(ua.x, ub.x), uc.x);
        us.y = haddu(haddu(ua.y, ub.y), uc.y);
        us.z = haddu(haddu(ua.z, ub.z), uc.z);
        us.w = haddu(haddu(ua.w, ub.w), uc.w);
        *(uint4*)(sm + OA + SW(row, c8, 512)) = us;
    }
    // prefetch W tile j=0 (kh=0 of ct=0)
#pragma unroll
    for (int it = 0; it < 8; it++) {
        int idx = tid + it * 256;
        int row = idx >> 4, c8 = idx & 15;
        cpa16(sb + OWB0 + SW(row, c8, 256), g_woTh + (size_t)row * C_DIM + c8 * 8);
    }
    CP_COMMIT();

    const int rAo = wm * 32 + (lane & 7) + lo3 * 8;  // + mt*16: A rows (s)
    const int rBt = (lane & 7) + lo3 * 8;            // + kk*16: B rows (ci, within kh)
    const int gq = lane >> 2, tq = lane & 3;

    for (int ct = 0; ct < 4; ct++) {
        float C[2][4][4];
#pragma unroll
        for (int i = 0; i < 2; i++)
#pragma unroll
            for (int j = 0; j < 4; j++)
#pragma unroll
                for (int k = 0; k < 4; k++) C[i][j][k] = 0.0f;

        for (int kh = 0; kh < 2; kh++) {
            int j = ct * 2 + kh;
            const uint32_t wb = (j & 1) ? OWB1 : OWB0;
            CP_WAIT0();
            __syncthreads();   // W[j] visible; everyone done with other buffer (and A on j=0)
            if (j < 7) {
                const uint32_t wb2 = (j & 1) ? OWB0 : OWB1;
                int j1 = j + 1;
                int ct1 = j1 >> 1, kh1 = j1 & 1;
#pragma unroll
                for (int it = 0; it < 8; it++) {
                    int idx = tid + it * 256;
                    int row = idx >> 4, c8 = idx & 15;
                    cpa16(sb + wb2 + SW(row, c8, 256),
                          g_woTh + (size_t)(kh1 * 128 + row) * C_DIM + ct1 * 128 + c8 * 8);
                }
                CP_COMMIT();
            }
#pragma unroll
            for (int kk = 0; kk < 8; kk++) {
                uint32_t a[2][4];
#pragma unroll
                for (int mt = 0; mt < 2; mt++)
                    ldm4(a[mt][0], a[mt][1], a[mt][2], a[mt][3],
                         sb + OA + SW(rAo + mt * 16, kh * 16 + kk * 2 + hi4, 512));
                int rr = kk * 16 + rBt;
#pragma unroll
                for (int nb = 0; nb < 2; nb++) {
                    uint32_t b0, b1, b2, b3;
                    ldm4t(b0, b1, b2, b3,
                          sb + wb + SW(rr, wn * 4 + nb * 2 + hi4, 256));
#pragma unroll
                    for (int mt = 0; mt < 2; mt++) {
                        mmah(C[mt][2 * nb],     a[mt][0], a[mt][1], a[mt][2], a[mt][3], b0, b1);
                        mmah(C[mt][2 * nb + 1], a[mt][0], a[mt][1], a[mt][2], a[mt][3], b2, b3);
                    }
                }
            }
        }
        // ---- epilogue for c-tile ct (Ps region is private; sync reuse across ct) ----
        __syncthreads();   // prev ct's Ps reads complete
#pragma unroll
        for (int mt = 0; mt < 2; mt++) {
            int sl = wm * 32 + mt * 16 + gq;
#pragma unroll
            for (int nt = 0; nt < 4; nt++) {
                int cl = wn * 32 + (nt >> 1) * 16 + (nt & 1) * 8 + 2 * tq;
                float* c = C[mt][nt];
                Ps[cl * 68 + sl]           = c[0];
                Ps[(cl + 1) * 68 + sl]     = c[1];
                Ps[cl * 68 + sl + 8]       = c[2];
                Ps[(cl + 1) * 68 + sl + 8] = c[3];
            }
        }
        __syncthreads();
#pragma unroll
        for (int it = 0; it < 8; it++) {
            int idx = tid + it * 256;
            int row = idx >> 4, f4 = idx & 15;
            int cglob = ct * 128 + row;
            float bb = b_out[cglob];
            float4 v = *(float4*)&Ps[row * 68 + f4 * 4];
            float4 iv = *(float4*)&invs[f4 * 4];
            v.x = v.x * iv.x + bb; v.y = v.y * iv.y + bb;
            v.z = v.z * iv.z + bb; v.w = v.w * iv.w + bb;
            uint2 ph;
            ph.x = packh2(v.x, v.y);
            ph.y = packh2(v.z, v.w);
            *(uint2*)&g_Ph[((size_t)n * C_DIM + cglob) * S_DIM + s0 + f4 * 4] = ph;
            float ssum = v.x + v.y + v.z + v.w;
            float ssq  = v.x * v.x + v.y * v.y + v.z * v.z + v.w * v.w;
#pragma unroll
            for (int d = 8; d >= 1; d >>= 1) {
                ssum += __shfl_xor_sync(0xffffffffu, ssum, d);
                ssq  += __shfl_xor_sync(0xffffffffu, ssq, d);
            }
            if ((lane & 15) == 0) {
                atomicAdd(&g_sum[cglob], ssum);
                atomicAdd(&g_sumsq[cglob], ssq);
            }
        }
    }
}

// ======================= K4/K5 =======================
__global__ void stats_kernel(const float* __restrict__ gamma, const float* __restrict__ beta) {
    int c = threadIdx.x;
    float m  = g_sum[c]   * (1.0f / BN_CNT);
    float v  = g_sumsq[c] * (1.0f / BN_CNT) - m * m;
    float sc = gamma[c] * rsqrtf(v + BN_EPS);
    g_scale[c] = sc;
    g_shift[c] = beta[c] - m * sc;
}
__global__ void bn_res_kernel(const float* __restrict__ x, float* __restrict__ out) {
    int i4 = blockIdx.x * 256 + threadIdx.x;
    int row = i4 / (S_DIM / 4);
    int c = row & (C_DIM - 1);
    float scl = g_scale[c], sh = g_shift[c];
    float4 xv = *(const float4*)&x[(size_t)i4 * 4];
    uint2 ph = *(const uint2*)&g_Ph[(size_t)i4 * 4];
    float2 p0 = __half22float2(*(half2*)&ph.x);
    float2 p1 = __half22float2(*(half2*)&ph.y);
    *(float4*)&out[(size_t)i4 * 4] = make_float4(
        xv.x + p0.x * scl + sh, xv.y + p0.y * scl + sh,
        xv.z + p1.x * scl + sh, xv.w + p1.y * scl + sh);
}

// ======================= launch =======================
extern "C" void kernel_launch(void* const* d_in, const int* in_sizes, int n_in,
                              void* d_out, int out_size) {
    const float* x       = (const float*)d_in[0];
    const float* w_theta = (const float*)d_in[1];
    const float* b_theta = (const float*)d_in[2];
    const float* w_phi   = (const float*)d_in[3];
    const float* b_phi   = (const float*)d_in[4];
    const float* w_g     = (const float*)d_in[5];
    const float* b_g     = (const float*)d_in[6];
    const float* w_out   = (const float*)d_in[7];
    const float* b_out   = (const float*)d_in[8];
    const float* gamma   = (const float*)d_in[9];
    const float* beta    = (const float*)d_in[10];
    float* out = (float*)d_out;

    cudaFuncSetAttribute((const void*)projh_kernel,
                         cudaFuncAttributeMaxDynamicSharedMemorySize, PROJ_SMEM);
    cudaFuncSetAttribute((const void*)attn_kernel,
                         cudaFuncAttributeMaxDynamicSharedMemorySize, ATTN_SMEM);
    cudaFuncSetAttribute((const void*)outproj_kernel,
                         cudaFuncAttributeMaxDynamicSharedMemorySize, OUTP_SMEM);

    transpose_kernel<<<512, 256>>>(w_theta, w_phi, w_g, w_out);
    init_kernel<<<294, 256>>>(b_theta, b_phi, b_g);
    projh_kernel<<<dim3(98, NB), 256, PROJ_SMEM>>>(x);
    attn_kernel<<<dim3(49, KSPLIT, NB), 256, ATTN_SMEM>>>();
    outproj_kernel<<<dim3(98, NB), 256, OUTP_SMEM>>>(b_out);
    stats_kernel<<<1, 512>>>(gamma, beta);
    bn_res_kernel<<<12544, 256>>>(x, out);
}

// round 16
// speedup vs baseline: 1.0331x; 1.0331x over previous
#include <cuda_runtime.h>
#include <cuda_fp16.h>
#include <cstdint>

// Nonlocal block: N=4, C=512, CI=256, S=6272. fp16 mma.sync everywhere.
// R16: outproj reverted to R14 form (many small CTAs win). Attention GEMM2
// split: own-key-half issued from GEMM1 C-registers BEFORE the pairwise
// barrier (FA2 fragment identity); partner half from smem after.
#define NB      4
#define C_DIM   512
#define CI_DIM  256
#define S_DIM   6272
#define BN_EPS  1e-5f
#define BN_CNT  25088.0f
#define SCL_TH  0.09016844f   // (1/16) * log2(e)
#define ONESH2  0x3C003C00u   // half2(1.0, 1.0)
#define KSPLIT  3
#define KT01    33

// ---- scratch ----
__device__ __half g_Qh[NB * S_DIM * CI_DIM];
__device__ __half g_Kh[NB * S_DIM * CI_DIM];
__device__ __half g_Vh[NB * S_DIM * CI_DIM];
__device__ __half g_Oph[KSPLIT * NB * S_DIM * CI_DIM];  // fp16 partial O
__device__ float  g_RSp[KSPLIT * NB * S_DIM];
__device__ __half g_Ph[NB * C_DIM * S_DIM];             // pre-BN, fp16
__device__ __half g_wAllh[C_DIM * 768];
__device__ __half g_woTh [CI_DIM * C_DIM];
__device__ float  g_bAll[768];
__device__ float  g_sum[C_DIM];
__device__ float  g_sumsq[C_DIM];
__device__ float  g_scale[C_DIM];
__device__ float  g_shift[C_DIM];

// ---- helpers ----
__device__ __forceinline__ uint32_t smem_u32(const void* p) {
    uint32_t a;
    asm("{ .reg .u64 t; cvta.to.shared.u64 t, %1; cvt.u32.u64 %0, t; }" : "=r"(a) : "l"(p));
    return a;
}
__device__ __forceinline__ uint32_t packh2(float lo, float hi) {
    uint32_t r;
    asm("cvt.rn.f16x2.f32 %0, %1, %2;" : "=r"(r) : "f"(hi), "f"(lo));
    return r;
}
__device__ __forceinline__ uint32_t ex2h2(uint32_t x) {
    uint32_t r;
    asm("ex2.approx.f16x2 %0, %1;" : "=r"(r) : "r"(x));
    return r;
}
__device__ __forceinline__ uint32_t haddu(uint32_t a, uint32_t b) {
    uint32_t r;
    asm("add.f16x2 %0, %1, %2;" : "=r"(r) : "r"(a), "r"(b));
    return r;
}
__device__ __forceinline__ void ldm4(uint32_t& r0, uint32_t& r1, uint32_t& r2, uint32_t& r3,
                                     uint32_t a) {
    asm volatile("ldmatrix.sync.aligned.m8n8.x4.shared.b16 {%0,%1,%2,%3}, [%4];"
                 : "=r"(r0), "=r"(r1), "=r"(r2), "=r"(r3) : "r"(a));
}
__device__ __forceinline__ void ldm4t(uint32_t& r0, uint32_t& r1, uint32_t& r2, uint32_t& r3,
                                      uint32_t a) {
    asm volatile("ldmatrix.sync.aligned.m8n8.x4.trans.shared.b16 {%0,%1,%2,%3}, [%4];"
                 : "=r"(r0), "=r"(r1), "=r"(r2), "=r"(r3) : "r"(a));
}
__device__ __forceinline__ void mmah(float* d, uint32_t a0, uint32_t a1, uint32_t a2,
                                     uint32_t a3, uint32_t b0, uint32_t b1) {
    asm volatile(
        "mma.sync.aligned.m16n8k16.row.col.f32.f16.f16.f32 "
        "{%0,%1,%2,%3}, {%4,%5,%6,%7}, {%8,%9}, {%0,%1,%2,%3};"
        : "+f"(d[0]), "+f"(d[1]), "+f"(d[2]), "+f"(d[3])
        : "r"(a0), "r"(a1), "r"(a2), "r"(a3), "r"(b0), "r"(b1));
}
__device__ __forceinline__ void cpa16(uint32_t dst, const void* src) {
    asm volatile("cp.async.cg.shared.global [%0], [%1], 16;" :: "r"(dst), "l"(src));
}
#define CP_COMMIT() asm volatile("cp.async.commit_group;" ::: "memory")
#define CP_WAIT0()  asm volatile("cp.async.wait_group 0;" ::: "memory")
#define BARP(id)    asm volatile("bar.sync %0, 64;" :: "r"(id) : "memory")
#define SW(row, c8, rowbytes) ((row) * (rowbytes) + ((((c8)) ^ ((row) & 7)) << 4))

// ======================= K0a: coalesced weight transpose =======================
__global__ void transpose_kernel(const float* __restrict__ wth, const float* __restrict__ wph,
                                 const float* __restrict__ wg,  const float* __restrict__ wout) {
    __shared__ float tile[32][33];
    int b = blockIdx.x;
    int tx = threadIdx.x & 31, ty = threadIdx.x >> 5;
    if (b < 384) {
        int m = b >> 7;
        int t = b & 127;
        int o0 = (t >> 4) << 5;
        int c0 = (t & 15) << 5;
        const float* src = (m == 0) ? wth : (m == 1) ? wph : wg;
#pragma unroll
        for (int i = 0; i < 4; i++) {
            int r = ty + i * 8;
            tile[r][tx] = src[(size_t)(o0 + r) * 512 + c0 + tx];
        }
        __syncthreads();
#pragma unroll
        for (int i = 0; i < 4; i++) {
            int r = ty + i * 8;
            g_wAllh[(size_t)(c0 + r) * 768 + m * 256 + o0 + tx] = __float2half(tile[tx][r]);
        }
    } else {
        int t = b - 384;
        int r0 = (t >> 3) << 5;
        int c0 = (t & 7) << 5;
#pragma unroll
        for (int i = 0; i < 4; i++) {
            int r = ty + i * 8;
            tile[r][tx] = wout[(size_t)(r0 + r) * 256 + c0 + tx];
        }
        __syncthreads();
#pragma unroll
        for (int i = 0; i < 4; i++) {
            int r = ty + i * 8;
            g_woTh[(size_t)(c0 + r) * 512 + r0 + tx] = __float2half(tile[tx][r]);
        }
    }
}

// ======================= K0b: init =======================
__global__ void init_kernel(const float* __restrict__ bth, const float* __restrict__ bph,
                            const float* __restrict__ bg) {
    int idx = blockIdx.x * 256 + threadIdx.x;
    if (idx < 768)
        g_bAll[idx] = (idx < 256) ? bth[idx] * SCL_TH
                    : (idx < 512) ? bph[idx - 256] : bg[idx - 512];
    if (idx < C_DIM) { g_sum[idx] = 0.0f; g_sumsq[idx] = 0.0f; }
    g_RSp[idx] = 0.0f;
}

// ======================= K1: QKV projection =======================
#define XS_ 0
#define WB0 65536
#define WB1 81920
#define PROJ_SMEM 98304
__global__ void __launch_bounds__(256, 2)
projh_kernel(const float* __restrict__ x) {
    extern __shared__ char sm[];
    const uint32_t sb = smem_u32(sm);
    const int tid = threadIdx.x, lane = tid & 31, w = tid >> 5;
    const int wm = w & 1, wn = w >> 1;
    const int lo3 = (lane >> 3) & 1, hi4 = lane >> 4;
    const int s0 = blockIdx.x * 64, n = blockIdx.y;
    const float* xn = x + (size_t)n * C_DIM * S_DIM;

#pragma unroll
    for (int it = 0; it < 32; it++) {
        int idx = tid + it * 256;
        int row = idx >> 4, s4 = idx & 15;
        float4 v = *(const float4*)(xn + (size_t)row * S_DIM + s0 + s4 * 4);
        half2* p = (half2*)(sm + XS_ + SW(row, s4 >> 1, 128) + (s4 & 1) * 8);
        p[0] = __floats2half2_rn(v.x, v.y);
        p[1] = __floats2half2_rn(v.z, v.w);
    }
#pragma unroll
    for (int it = 0; it < 4; it++) {
        int idx = tid + it * 256;
        int rowc = idx >> 4, c8 = idx & 15;
        cpa16(sb + WB0 + SW(rowc, c8, 256), g_wAllh + (size_t)rowc * 768 + c8 * 8);
    }
    CP_COMMIT();

    const int rAx = (lane & 7) + hi4 * 8;
    const int rBw = (lane & 7) + lo3 * 8;
    const int gq = lane >> 2, tq = lane & 3;

    for (int ob = 0; ob < 6; ob++) {
        float C[2][4][4];
#pragma unroll
        for (int i = 0; i < 2; i++)
#pragma unroll
            for (int j = 0; j < 4; j++)
#pragma unroll
                for (int k = 0; k < 4; k++) C[i][j][k] = 0.0f;

        for (int cs = 0; cs < 8; cs++) {
            int j = ob * 8 + cs;
            const uint32_t wb = (j & 1) ? WB1 : WB0;
            CP_WAIT0();
            __syncthreads();
            if (j < 47) {
                const uint32_t wb2 = (j & 1) ? WB0 : WB1;
                int j1 = j + 1;
                int ob1 = j1 >> 3, cs1 = j1 & 7;
#pragma unroll
                for (int it = 0; it < 4; it++) {
                    int idx = tid + it * 256;
                    int rowc = idx >> 4, c8 = idx & 15;
                    cpa16(sb + wb2 + SW(rowc, c8, 256),
                          g_wAllh + (size_t)(cs1 * 64 + rowc) * 768 + ob1 * 128 + c8 * 8);
                }
                CP_COMMIT();
            }
#pragma unroll
            for (int kk = 0; kk < 4; kk++) {
                uint32_t a[2][4];
#pragma unroll
                for (int mt = 0; mt < 2; mt++)
                    ldm4t(a[mt][0], a[mt][1], a[mt][2], a[mt][3],
                          sb + XS_ + SW(cs * 64 + kk * 16 + rAx,
                                        wm * 4 + mt * 2 + lo3, 128));
#pragma unroll
                for (int nb = 0; nb < 2; nb++) {
                    uint32_t b0, b1, b2, b3;
                    ldm4t(b0, b1, b2, b3,
                          sb + wb + SW(kk * 16 + rBw, wn * 4 + nb * 2 + hi4, 256));
#pragma unroll
                    for (int mt = 0; mt < 2; mt++) {
                        mmah(C[mt][2 * nb],     a[mt][0], a[mt][1], a[mt][2], a[mt][3], b0, b1);
                        mmah(C[mt][2 * nb + 1], a[mt][0], a[mt][1], a[mt][2], a[mt][3], b2, b3);
                    }
                }
            }
        }
        const float osc = (ob < 2) ? SCL_TH : 1.0f;
        const int buf = ob >> 1;
        __half* outb = (buf == 0) ? g_Qh : (buf == 1) ? g_Kh : g_Vh;
        const int colbase = (ob & 1) * 128;
#pragma unroll
        for (int mt = 0; mt < 2; mt++) {
            int srow = s0 + wm * 32 + mt * 16 + gq;
            __half* p0 = outb + ((size_t)n * S_DIM + srow) * CI_DIM + colbase;
            __half* p8 = p0 + 8 * CI_DIM;
#pragma unroll
            for (int nt = 0; nt < 4; nt++) {
                int oloc = wn * 32 + nt * 8 + 2 * tq;
                float bb0 = g_bAll[ob * 128 + oloc], bb1 = g_bAll[ob * 128 + oloc + 1];
                float* c = C[mt][nt];
                *(half2*)(p0 + oloc) = __floats2half2_rn(c[0] * osc + bb0, c[1] * osc + bb1);
                *(half2*)(p8 + oloc) = __floats2half2_rn(c[2] * osc + bb0, c[3] * osc + bb1);
            }
        }
    }
}

// ======================= K2: fp16 flash attention (key-split-3) =======================
// Warp (mb from cross-SMSP map, hf). GEMM2 own-key-half (kk2 = 2hf, 2hf+1)
// issued from GEMM1 C-registers BEFORE the pairwise barrier; partner half
// (kk2 of 1-hf) read from smem P after the barrier.
#define AQ   0
#define BUF0 65536
#define BUF1 131072
#define AP   196608
#define ATTN_SMEM 212992
__global__ void __launch_bounds__(256, 1)
attn_kernel() {
    extern __shared__ char sm[];
    const uint32_t sb = smem_u32(sm);
    const int tid = threadIdx.x, lane = tid & 31, w = tid >> 5;
    const int hf = w >> 2;
    const int mb = (w + hf) & 3;
    const int g = lane >> 2, t = lane & 3;
    const int lo3 = (lane >> 3) & 1, hi4 = lane >> 4;
    const int s0 = blockIdx.x * 128;
    const int bh = blockIdx.y;
    const int n  = blockIdx.z;
    const int ntile = (bh < 2) ? KT01 : (98 - 2 * KT01);
    const int kb0 = bh * KT01 * 64;
    const __half* Qg = g_Qh + (size_t)n * S_DIM * CI_DIM;
    const __half* Kg = g_Kh + (size_t)n * S_DIM * CI_DIM;
    const __half* Vg = g_Vh + (size_t)n * S_DIM * CI_DIM;

#pragma unroll
    for (int it = 0; it < 16; it++) {
        int idx = tid + it * 256;
        int row = idx >> 5, c8 = idx & 31;
        cpa16(sb + AQ + SW(row, c8, 512),
              Qg + (size_t)(s0 + row) * CI_DIM + c8 * 8);
    }
#pragma unroll
    for (int it = 0; it < 8; it++) {
        int idx = tid + it * 256;
        int r = idx >> 5, c8 = idx & 31;
        uint32_t off = SW(r, c8, 512);
        cpa16(sb + BUF0 + off,         Kg + (size_t)(kb0 + r) * CI_DIM + c8 * 8);
        cpa16(sb + BUF0 + 32768 + off, Vg + (size_t)(kb0 + r) * CI_DIM + c8 * 8);
    }
    CP_COMMIT();

    float O[2][16][4];
#pragma unroll
    for (int mt = 0; mt < 2; mt++)
#pragma unroll
        for (int i = 0; i < 16; i++)
#pragma unroll
            for (int j = 0; j < 4; j++) O[mt][i][j] = 0.0f;
    float Ors[2][4];
#pragma unroll
    for (int mt = 0; mt < 2; mt++)
#pragma unroll
        for (int j = 0; j < 4; j++) Ors[mt][j] = 0.0f;

    const int rA  = mb * 32 + (lane & 7) + lo3 * 8;
    const int rK  = hf * 32 + (lane & 7) + hi4 * 8;
    const int rV  = (lane & 7) + lo3 * 8;
    const int rP  = mb * 32 + (lane & 7) + lo3 * 8;

    for (int kt = 0; kt < ntile; kt++) {
        const uint32_t bk = (kt & 1) ? BUF1 : BUF0;
        CP_WAIT0();
        __syncthreads();
        if (kt < ntile - 1) {
            const uint32_t bn_ = (kt & 1) ? BUF0 : BUF1;
            int ks1 = kb0 + (kt + 1) * 64;
#pragma unroll
            for (int it = 0; it < 8; it++) {
                int idx = tid + it * 256;
                int r = idx >> 5, c8 = idx & 31;
                uint32_t off = SW(r, c8, 512);
                cpa16(sb + bn_ + off,         Kg + (size_t)(ks1 + r) * CI_DIM + c8 * 8);
                cpa16(sb + bn_ + 32768 + off, Vg + (size_t)(ks1 + r) * CI_DIM + c8 * 8);
            }
            CP_COMMIT();
        }
        // ---- GEMM1: S(32q x 32k) = Q[mb] K[hf]^T ----
        float S[2][4][4];
#pragma unroll
        for (int mt = 0; mt < 2; mt++)
#pragma unroll
            for (int i = 0; i < 4; i++)
#pragma unroll
                for (int j = 0; j < 4; j++) S[mt][i][j] = 0.0f;
#pragma unroll
        for (int kk = 0; kk < 16; kk++) {
            uint32_t a[2][4];
#pragma unroll
            for (int mt = 0; mt < 2; mt++)
                ldm4(a[mt][0], a[mt][1], a[mt][2], a[mt][3],
                     sb + AQ + SW(rA + mt * 16, kk * 2 + hi4, 512));
#pragma unroll
            for (int j = 0; j < 2; j++) {
                uint32_t b0, b1, b2, b3;
                ldm4(b0, b1, b2, b3, sb + bk + SW(rK + j * 16, kk * 2 + lo3, 512));
#pragma unroll
                for (int mt = 0; mt < 2; mt++) {
                    mmah(S[mt][2 * j],     a[mt][0], a[mt][1], a[mt][2], a[mt][3], b0, b1);
                    mmah(S[mt][2 * j + 1], a[mt][0], a[mt][1], a[mt][2], a[mt][3], b2, b3);
                }
            }
        }
        // ---- exp (f16x2 SFU), ones-MMA rowsum, P -> smem ----
        uint32_t pk[2][4][2];
#pragma unroll
        for (int mt = 0; mt < 2; mt++) {
#pragma unroll
            for (int nt = 0; nt < 4; nt++) {
                pk[mt][nt][0] = ex2h2(packh2(S[mt][nt][0], S[mt][nt][1]));
                pk[mt][nt][1] = ex2h2(packh2(S[mt][nt][2], S[mt][nt][3]));
            }
            mmah(Ors[mt], pk[mt][0][0], pk[mt][0][1], pk[mt][1][0], pk[mt][1][1],
                 ONESH2, ONESH2);
            mmah(Ors[mt], pk[mt][2][0], pk[mt][2][1], pk[mt][3][0], pk[mt][3][1],
                 ONESH2, ONESH2);
#pragma unroll
            for (int nt = 0; nt < 4; nt++) {
                int r0 = mb * 32 + mt * 16 + g;
                int c8p = hf * 4 + nt;
                *(uint32_t*)(sm + AP + SW(r0, c8p, 128) + t * 4)     = pk[mt][nt][0];
                *(uint32_t*)(sm + AP + SW(r0 + 8, c8p, 128) + t * 4) = pk[mt][nt][1];
            }
        }
        // ---- GEMM2 own key half (kk2 = 2hf+j): A from registers, BEFORE barrier ----
#pragma unroll
        for (int j = 0; j < 2; j++) {
            int rVk = rV + (hf * 2 + j) * 16;
#pragma unroll
            for (int nb = 0; nb < 8; nb++) {
                uint32_t b0, b1, b2, b3;
                ldm4t(b0, b1, b2, b3,
                      sb + bk + 32768 + SW(rVk, hf * 16 + nb * 2 + hi4, 512));
#pragma unroll
                for (int mt = 0; mt < 2; mt++) {
                    mmah(O[mt][2 * nb],     pk[mt][2 * j][0], pk[mt][2 * j][1],
                         pk[mt][2 * j + 1][0], pk[mt][2 * j + 1][1], b0, b1);
                    mmah(O[mt][2 * nb + 1], pk[mt][2 * j][0], pk[mt][2 * j][1],
                         pk[mt][2 * j + 1][0], pk[mt][2 * j + 1][1], b2, b3);
                }
            }
        }
        BARP(mb + 1);   // pairwise; partner's P now visible
        // ---- GEMM2 partner key half (kk2 = 2(1-hf)+j): A from smem ----
#pragma unroll
        for (int j = 0; j < 2; j++) {
            int kk2 = (1 - hf) * 2 + j;
            uint32_t a[2][4];
#pragma unroll
            for (int mt = 0; mt < 2; mt++)
                ldm4(a[mt][0], a[mt][1], a[mt][2], a[mt][3],
                     sb + AP + SW(rP + mt * 16, kk2 * 2 + hi4, 128));
            int rVk = rV + kk2 * 16;
#pragma unroll
            for (int nb = 0; nb < 8; nb++) {
                uint32_t b0, b1, b2, b3;
                ldm4t(b0, b1, b2, b3,
                      sb + bk + 32768 + SW(rVk, hf * 16 + nb * 2 + hi4, 512));
#pragma unroll
                for (int mt = 0; mt < 2; mt++) {
                    mmah(O[mt][2 * nb],     a[mt][0], a[mt][1], a[mt][2], a[mt][3], b0, b1);
                    mmah(O[mt][2 * nb + 1], a[mt][0], a[mt][1], a[mt][2], a[mt][3], b2, b3);
                }
            }
        }
    }
    // ---- epilogue ----
    float* RSp = g_RSp + ((size_t)bh * NB + n) * S_DIM + s0;
    if (t == 0) {
#pragma unroll
        for (int mt = 0; mt < 2; mt++) {
            atomicAdd(&RSp[mb * 32 + mt * 16 + g],     Ors[mt][0]);
            atomicAdd(&RSp[mb * 32 + mt * 16 + g + 8], Ors[mt][2]);
        }
    }
    __half* Op = g_Oph + (((size_t)bh * NB + n) * S_DIM + s0) * CI_DIM;
#pragma unroll
    for (int mt = 0; mt < 2; mt++) {
        int r0 = mb * 32 + mt * 16 + g;
#pragma unroll
        for (int nt = 0; nt < 16; nt++) {
            int col = hf * 128 + nt * 8 + 2 * t;
            *(uint32_t*)&Op[(size_t)r0 * CI_DIM + col] =
                packh2(O[mt][nt][0], O[mt][nt][1]);
            *(uint32_t*)&Op[(size_t)(r0 + 8) * CI_DIM + col] =
                packh2(O[mt][nt][2], O[mt][nt][3]);
        }
    }
}

// ======================= K3: out projection (R14 form) + BN stats =======================
#define OA  0
#define OB_ 32768
#define OINV 67584
#define OUTP_SMEM 68608
__global__ void __launch_bounds__(256)
outproj_kernel(const float* __restrict__ b_out) {
    extern __shared__ char sm[];
    const uint32_t sb = smem_u32(sm);
    const int tid = threadIdx.x, lane = tid & 31, w = tid >> 5;
    const int wm = w & 3, wn = w >> 2;
    const int lo3 = (lane >> 3) & 1, hi4 = lane >> 4;
    const int s0 = blockIdx.x * 128, c0g = blockIdx.y * 128, n = blockIdx.z;
    const size_t STR = (size_t)NB * S_DIM * CI_DIM;
    const __half* Opm = g_Oph + ((size_t)n * S_DIM + s0) * CI_DIM;
    float* invs = (float*)(sm + OINV);

    if (tid < 128) {
        int s_lin = n * S_DIM + s0 + tid;
        float r = g_RSp[s_lin] + g_RSp[NB * S_DIM + s_lin]
                + g_RSp[2 * NB * S_DIM + s_lin];
        invs[tid] = 1.0f / r;
    }

    float C[2][8][4];
#pragma unroll
    for (int i = 0; i < 2; i++)
#pragma unroll
        for (int j = 0; j < 8; j++)
#pragma unroll
            for (int k = 0; k < 4; k++) C[i][j][k] = 0.0f;

    const int rBt = (lane & 7) + lo3 * 8;

    for (int ks = 0; ks < 2; ks++) {
        int k0 = ks * 128;
        __syncthreads();
#pragma unroll
        for (int it = 0; it < 8; it++) {
            int idx = tid + it * 256;
            int row = idx >> 4, c8 = idx & 15;
            const __half* basep = Opm + (size_t)row * CI_DIM + k0 + c8 * 8;
            uint4 ua = *(const uint4*)basep;
            uint4 ub = *(const uint4*)(basep + STR);
            uint4 uc = *(const uint4*)(basep + 2 * STR);
            uint4 us;
            us.x = haddu(haddu(ua.x, ub.x), uc.x);
            us.y = haddu(haddu(ua.y, ub.y), uc.y);
            us.z = haddu(haddu(ua.z, ub.z), uc.z);
            us.w = haddu(haddu(ua.w, ub.w), uc.w);
            *(uint4*)(sm + OA + SW(row, c8, 256)) = us;
            cpa16(sb + OB_ + SW(row, c8, 256),
                  g_woTh + (size_t)(k0 + row) * C_DIM + c0g + c8 * 8);
        }
        CP_COMMIT();
        CP_WAIT0();
        __syncthreads();
#pragma unroll
        for (int kk = 0; kk < 8; kk++) {
            uint32_t a[2][4];
#pragma unroll
            for (int mt = 0; mt < 2; mt++) {
                int rr = wm * 32 + mt * 16 + (lane & 7) + lo3 * 8;
                ldm4(a[mt][0], a[mt][1], a[mt][2], a[mt][3],
                     sb + OA + SW(rr, kk * 2 + hi4, 256));
            }
#pragma unroll
            for (int nb = 0; nb < 4; nb++) {
                int rr = kk * 16 + rBt;
                int c8 = wn * 8 + nb * 2 + hi4;
                uint32_t b0, b1, b2, b3;
                ldm4t(b0, b1, b2, b3, sb + OB_ + SW(rr, c8, 256));
#pragma unroll
                for (int mt = 0; mt < 2; mt++) {
                    mmah(C[mt][2 * nb],     a[mt][0], a[mt][1], a[mt][2], a[mt][3], b0, b1);
                    mmah(C[mt][2 * nb + 1], a[mt][0], a[mt][1], a[mt][2], a[mt][3], b2, b3);
                }
            }
        }
    }
    __syncthreads();
    float* Ps = (float*)sm;   // [128 c][132 s]
    const int gq = lane >> 2, tq = lane & 3;
#pragma unroll
    for (int mt = 0; mt < 2; mt++) {
        int sl = wm * 32 + mt * 16 + gq;
#pragma unroll
        for (int nt = 0; nt < 8; nt++) {
            int cl = wn * 64 + (nt >> 1) * 16 + (nt & 1) * 8 + 2 * tq;
            float* c = C[mt][nt];
            Ps[cl * 132 + sl]           = c[0];
            Ps[(cl + 1) * 132 + sl]     = c[1];
            Ps[cl * 132 + sl + 8]       = c[2];
            Ps[(cl + 1) * 132 + sl + 8] = c[3];
        }
    }
    __syncthreads();
#pragma unroll
    for (int it = 0; it < 16; it++) {
        int row = w + it * 8;
        int cglob = c0g + row;
        float bb = b_out[cglob];
        float4 v = *(float4*)&Ps[row * 132 + lane * 4];
        float4 iv = *(float4*)&invs[lane * 4];
        v.x = v.x * iv.x + bb; v.y = v.y * iv.y + bb;
        v.z = v.z * iv.z + bb; v.w = v.w * iv.w + bb;
        uint2 ph;
        ph.x = packh2(v.x, v.y);
        ph.y = packh2(v.z, v.w);
        *(uint2*)&g_Ph[((size_t)n * C_DIM + cglob) * S_DIM + s0 + lane * 4] = ph;
        float ssum = v.x + v.y + v.z + v.w;
        float ssq  = v.x * v.x + v.y * v.y + v.z * v.z + v.w * v.w;
#pragma unroll
        for (int d = 16; d >= 1; d >>= 1) {
            ssum += __shfl_xor_sync(0xffffffffu, ssum, d);
            ssq  += __shfl_xor_sync(0xffffffffu, ssq, d);
        }
        if (lane == 0) {
            atomicAdd(&g_sum[cglob], ssum);
            atomicAdd(&g_sumsq[cglob], ssq);
        }
    }
}

// ======================= K4/K5 =======================
__global__ void stats_kernel(const float* __restrict__ gamma, const float* __restrict__ beta) {
    int c = threadIdx.x;
    float m  = g_sum[c]   * (1.0f / BN_CNT);
    float v  = g_sumsq[c] * (1.0f / BN_CNT) - m * m;
    float sc = gamma[c] * rsqrtf(v + BN_EPS);
    g_scale[c] = sc;
    g_shift[c] = beta[c] - m * sc;
}
__global__ void bn_res_kernel(const float* __restrict__ x, float* __restrict__ out) {
    int i4 = blockIdx.x * 256 + threadIdx.x;
    int row = i4 / (S_DIM / 4);
    int c = row & (C_DIM - 1);
    float scl = g_scale[c], sh = g_shift[c];
    float4 xv = *(const float4*)&x[(size_t)i4 * 4];
    uint2 ph = *(const uint2*)&g_Ph[(size_t)i4 * 4];
    float2 p0 = __half22float2(*(half2*)&ph.x);
    float2 p1 = __half22float2(*(half2*)&ph.y);
    *(float4*)&out[(size_t)i4 * 4] = make_float4(
        xv.x + p0.x * scl + sh, xv.y + p0.y * scl + sh,
        xv.z + p1.x * scl + sh, xv.w + p1.y * scl + sh);
}

// ======================= launch =======================
extern "C" void kernel_launch(void* const* d_in, const int* in_sizes, int n_in,
                              void* d_out, int out_size) {
    const float* x       = (const float*)d_in[0];
    const float* w_theta = (const float*)d_in[1];
    const float* b_theta = (const float*)d_in[2];
    const float* w_phi   = (const float*)d_in[3];
    const float* b_phi   = (const float*)d_in[4];
    const float* w_g     = (const float*)d_in[5];
    const float* b_g     = (const float*)d_in[6];
    const float* w_out   = (const float*)d_in[7];
    const float* b_out   = (const float*)d_in[8];
    const float* gamma   = (const float*)d_in[9];
    const float* beta    = (const float*)d_in[10];
    float* out = (float*)d_out;

    cudaFuncSetAttribute((const void*)projh_kernel,
                         cudaFuncAttributeMaxDynamicSharedMemorySize, PROJ_SMEM);
    cudaFuncSetAttribute((const void*)attn_kernel,
                         cudaFuncAttributeMaxDynamicSharedMemorySize, ATTN_SMEM);
    cudaFuncSetAttribute((const void*)outproj_kernel,
                         cudaFuncAttributeMaxDynamicSharedMemorySize, OUTP_SMEM);

    transpose_kernel<<<512, 256>>>(w_theta, w_phi, w_g, w_out);
    init_kernel<<<294, 256>>>(b_theta, b_phi, b_g);
    projh_kernel<<<dim3(98, NB), 256, PROJ_SMEM>>>(x);
    attn_kernel<<<dim3(49, KSPLIT, NB), 256, ATTN_SMEM>>>();
    outproj_kernel<<<dim3(49, 4, NB), 256, OUTP_SMEM>>>(b_out);
    stats_kernel<<<1, 512>>>(gamma, beta);
    bn_res_kernel<<<12544, 256>>>(x, out);
}